// round 17
// baseline (speedup 1.0000x reference)
#include <cuda_runtime.h>
#include <cstdint>

#define HW   14
#define NCH  128
#define NJ   32
#define NSP  448             // tiles: 4 (n,h) slices each
#define NBLK 148             // persistent, 1 CTA/SM
#define THREADS 384

#define A_STRIDE 132         // words per A row (128 + 4 pad) -> conflict-free ldmatrix
#define A_ROWS   66          // 4 x 16 slot-rows + 2 tap-overrun rows
#define A_WORDS  (A_ROWS * A_STRIDE)      // 8712 per buffer
#define B_STRIDE 132
#define B_WORDS  (96 * B_STRIDE)          // 12672 (rows = kk*32 + j); reused as scratch
#define SMEM_BYTES ((B_WORDS + 2 * A_WORDS) * 4)   // 120384 B

__device__ __align__(16) unsigned Wg[96 * 128];   // tf32 W, row (kk*32+j), col i
__device__ unsigned g_ctr[32];

__global__ void prep_kernel(const float* __restrict__ W) {
    int idx = blockIdx.x * blockDim.x + threadIdx.x;
    if (idx == 0) g_ctr[0] = NBLK;        // static first tiles 0..147 pre-assigned
    if (idx < 96 * 128) {
        int i  = idx & 127;
        int j  = (idx >> 7) & 31;
        int kk = idx >> 12;
        unsigned b;
        asm("cvt.rna.tf32.f32 %0, %1;" : "=r"(b) : "f"(W[j * 384 + kk * 128 + i]));
        Wg[idx] = b;
    }
}

__device__ __forceinline__ uint32_t smem_u32(const void* p) {
    uint32_t a;
    asm("{ .reg .u64 t; cvta.to.shared.u64 t, %1; cvt.u32.u64 %0, t; }" : "=r"(a) : "l"(p));
    return a;
}
__device__ __forceinline__ void ldsm_x4(uint32_t addr, unsigned& r0, unsigned& r1,
                                        unsigned& r2, unsigned& r3) {
    asm volatile("ldmatrix.sync.aligned.m8n8.x4.shared.b16 {%0,%1,%2,%3}, [%4];"
                 : "=r"(r0), "=r"(r1), "=r"(r2), "=r"(r3) : "r"(addr));
}
__device__ __forceinline__ void mma_tf32(float* c, unsigned a0, unsigned a1, unsigned a2,
                                         unsigned a3, unsigned b0, unsigned b1) {
    asm volatile("mma.sync.aligned.m16n8k8.row.col.f32.tf32.tf32.f32 "
                 "{%0,%1,%2,%3}, {%4,%5,%6,%7}, {%8,%9}, {%0,%1,%2,%3};"
                 : "+f"(c[0]), "+f"(c[1]), "+f"(c[2]), "+f"(c[3])
                 : "r"(a0), "r"(a1), "r"(a2), "r"(a3), "r"(b0), "r"(b1));
}

// Prefetch one slice's x row for channel i into registers (streaming).
__device__ __forceinline__ void prefetch_x(const float* __restrict__ x, int slice, int i,
                                           float2 (&v)[7]) {
    int n = slice / 14, h = slice % 14;
    const float2* xp = (const float2*)(x + ((n * NCH + i) * HW + h) * HW);
#pragma unroll
    for (int m2 = 0; m2 < 7; ++m2) v[m2] = __ldcs(xp + m2);
}

// STS one slice-row into an A buffer (thread = channel i, slot-group gg 0..3).
__device__ __forceinline__ void stage_A(unsigned* As, int i, int gg, const float2 (&v)[7]) {
    unsigned* base = As + (16 * gg) * A_STRIDE + i;
#pragma unroll
    for (int m2 = 0; m2 < 7; ++m2) {
        int w0 = 2 * m2;
        int p0 = w0 + 2;                     // even w never wraps
        int p1 = (w0 == 12) ? 1 : (w0 + 3);  // w=13 wraps to slot 1
        unsigned b0, b1;
        asm("cvt.rna.tf32.f32 %0, %1;" : "=r"(b0) : "f"(v[m2].x));
        asm("cvt.rna.tf32.f32 %0, %1;" : "=r"(b1) : "f"(v[m2].y));
        base[p0 * A_STRIDE] = b0;            // banks (4p+i)%32: CF
        base[p1 * A_STRIDE] = b1;
    }
}

__global__ void __launch_bounds__(THREADS)
conv_mma_kernel(const float* __restrict__ x, float* __restrict__ out) {
    extern __shared__ unsigned sm[];
    unsigned* Bs = sm;                        // [96][132]; later reused as scratch
    unsigned* A0 = sm + B_WORDS;
    unsigned* A1 = A0 + A_WORDS;
    float* scratch = (float*)sm;              // [pk][gid][slot][16 regs][32 lanes] = 8192 f
    __shared__ int s_nxt[2];

    const int t    = threadIdx.x;
    const int lane = t & 31;
    const int wid  = t >> 5;                  // 0..11
    const int kk   = wid >> 2;                // tap 0..2
    const int gid  = wid & 3;                 // (g2, nh) reduction group
    const int g2   = gid >> 1;                // base m-tile: handles g2 and g2+2
    const int nh   = gid & 1;                 // j-half
    const int si   = t & 127;                 // staging channel
    const int sg   = t >> 7;                  // staging slice group 0..2 (task 1)

    // ---- stage B to smem, zero A guard rows ----
    for (int idx = t; idx < 96 * 32; idx += THREADS) {
        int row = idx >> 5, seg = idx & 31;
        ((uint4*)(Bs + row * B_STRIDE))[seg] = ((const uint4*)(Wg + row * 128))[seg];
    }
    {
        const int zr[10] = {0, 15, 16, 31, 32, 47, 48, 63, 64, 65};
        for (int idx = t; idx < 10 * 128; idx += THREADS) {
            int r = zr[idx >> 7], c = idx & 127;
            A0[r * A_STRIDE + c] = 0;
            A1[r * A_STRIDE + c] = 0;
        }
    }
    __syncthreads();

    // ---- preload this warp's B fragments into registers (once per kernel) ----
    unsigned bf[16][4];
    {
        const uint32_t bb = smem_u32(Bs) +
            (((kk * 32 + 16 * nh + 8 * (lane >> 4) + (lane & 7)) * B_STRIDE +
              4 * ((lane >> 3) & 1)) << 2);
#pragma unroll
        for (int q = 0; q < 16; ++q)
            ldsm_x4(bb + q * 32, bf[q][0], bf[q][1], bf[q][2], bf[q][3]);
    }
    __syncthreads();                          // B reads done -> scratch overlay safe

    const uint32_t a_off_lo = ((16 * g2 + (lane & 15)) * A_STRIDE + 4 * (lane >> 4)) << 2;
    const uint32_t a_off_hi = a_off_lo + ((32 * A_STRIDE) << 2);   // m-tile g2+2
    const uint32_t tapoff = kk * (A_STRIDE * 4);
    const uint32_t aL0 = smem_u32(A0) + a_off_lo + tapoff;
    const uint32_t aH0 = smem_u32(A0) + a_off_hi + tapoff;
    const uint32_t aL1 = smem_u32(A1) + a_off_lo + tapoff;
    const uint32_t aH1 = smem_u32(A1) + a_off_hi + tapoff;

    // ---- prologue: static tile, stage A0, steal ahead ----
    int cur = blockIdx.x;                     // 0..147 < NSP
    float2 v[2][7];
    prefetch_x(x, cur * 4 + sg, si, v[0]);
    if (t < 128) prefetch_x(x, cur * 4 + 3, si, v[1]);
    stage_A(A0, si, sg, v[0]);
    if (t < 128) stage_A(A0, si, 3, v[1]);
    if (t == 0) s_nxt[0] = atomicAdd(&g_ctr[0], 1);
    __syncthreads();

    int pk = 0;
    while (cur < NSP) {
        int nxt = s_nxt[pk];
        if (t == 0) s_nxt[pk ^ 1] = atomicAdd(&g_ctr[0], 1);      // steal 2 ahead
        if (nxt < NSP) {
            prefetch_x(x, nxt * 4 + sg, si, v[0]);
            if (t < 128) prefetch_x(x, nxt * 4 + 3, si, v[1]);
        }

        // ---- compute partials (this tap): 2 m-tiles x 16 q-iters, B in regs ----
        float d[16];
#pragma unroll
        for (int a = 0; a < 16; ++a) d[a] = 0.f;
        const uint32_t aL = pk ? aL1 : aL0;
        const uint32_t aH = pk ? aH1 : aH0;
#pragma unroll
        for (int q = 0; q < 16; ++q) {
            unsigned a0, a1, a2, a3, c0, c1, c2, c3;
            ldsm_x4(aL + q * 32, a0, a1, a2, a3);
            ldsm_x4(aH + q * 32, c0, c1, c2, c3);
            mma_tf32(d,      a0, a1, a2, a3, bf[q][0], bf[q][1]);
            mma_tf32(d + 4,  a0, a1, a2, a3, bf[q][2], bf[q][3]);
            mma_tf32(d + 8,  c0, c1, c2, c3, bf[q][0], bf[q][1]);
            mma_tf32(d + 12, c0, c1, c2, c3, bf[q][2], bf[q][3]);
        }

        // ---- stage next tile into the other buffer ----
        if (nxt < NSP) {
            unsigned* An = pk ? A0 : A1;
            stage_A(An, si, sg, v[0]);
            if (t < 128) stage_A(An, si, 3, v[1]);
        }

        // ---- partial store (2 non-reducer taps) ----
        const int rr = cur % 3;               // reducer tap for this tile
        if (kk != rr) {
            int slot = (kk + 3 - rr) % 3 - 1; // 0 or 1
            float* sp2 = scratch + ((pk * 4 + gid) * 2 + slot) * 512 + lane;
#pragma unroll
            for (int a = 0; a < 16; ++a) sp2[a * 32] = d[a];
        }
        __syncthreads();                      // publish A[pk^1], s_nxt, partials

        // ---- reducer tap: sum partials, scatter with height-roll(+1) ----
        if (kk == rr) {
            const float* sp2 = scratch + (pk * 4 + gid) * 2 * 512 + lane;
#pragma unroll
            for (int a = 0; a < 16; ++a) d[a] += sp2[a * 32] + sp2[512 + a * 32];
            int r0 = lane >> 2, r1 = r0 + 8;
#pragma unroll
            for (int mt = 0; mt < 2; ++mt) {
                int slice = cur * 4 + g2 + 2 * mt;
                int n = slice / 14, h = slice % 14;
                int h2 = (h + 1 == 14) ? 0 : h + 1;
#pragma unroll
                for (int tl = 0; tl < 2; ++tl) {
                    int j0 = 16 * nh + 8 * tl + 2 * (lane & 3);
                    float* o0 = out + ((n * NJ + j0) * HW + h2) * HW;
                    const float* dd = d + 8 * mt + 4 * tl;
                    o0[r0]       = dd[0];
                    o0[r0 + 196] = dd[1];              // j0+1
                    if (r1 < 14) {
                        o0[r1]       = dd[2];
                        o0[r1 + 196] = dd[3];
                    }
                }
            }
        }
        cur = nxt;
        pk ^= 1;
    }
}

extern "C" void kernel_launch(void* const* d_in, const int* in_sizes, int n_in,
                              void* d_out, int out_size) {
    const float* x = (const float*)d_in[0];   // (128,128,14,14) fp32
    const float* W = (const float*)d_in[1];   // (32,3,128) fp32
    float* out = (float*)d_out;               // (128,32,14,14) fp32

    prep_kernel<<<12, 1024>>>(W);

    cudaFuncSetAttribute(conv_mma_kernel,
                         cudaFuncAttributeMaxDynamicSharedMemorySize, SMEM_BYTES);
    conv_mma_kernel<<<NBLK, THREADS, SMEM_BYTES>>>(x, out);
}